// round 6
// baseline (speedup 1.0000x reference)
#include <cuda_runtime.h>

// Per-node weight accumulator. Zero at module load; phase 2 re-zeroes after
// consuming, so every graph replay starts from zeros.
__device__ float g_w[4 * 1024 * 1024];
__device__ double g_acc[8];
__device__ unsigned int g_count;

// ---------------- Phase 1: per-element det(J)/6 scattered to node weights ----
// Grid-stride with atomics interleaved per iteration: the REDG ops pipeline
// under the next iteration's index/coord loads (R3 shape, ~REDG issue floor).
__global__ __launch_bounds__(256) void phase1_kernel(
    const float* __restrict__ coords,    // (N_NODES, 2)
    const int*   __restrict__ elements,  // (E, 3)
    int n_elements)
{
    const int stride = gridDim.x * blockDim.x;
    for (int e = blockIdx.x * blockDim.x + threadIdx.x; e < n_elements; e += stride) {
        const int i0 = elements[3 * e + 0];
        const int i1 = elements[3 * e + 1];
        const int i2 = elements[3 * e + 2];

        const float2 c0 = *reinterpret_cast<const float2*>(coords + 2 * i0);
        const float2 c1 = *reinterpret_cast<const float2*>(coords + 2 * i1);
        const float2 c2 = *reinterpret_cast<const float2*>(coords + 2 * i2);

        // det(J) for Tri3; 3-pt symmetric rule gives sum_q w_q N_q[n] = 1/6.
        const float det = (c1.x - c0.x) * (c2.y - c0.y)
                        - (c1.y - c0.y) * (c2.x - c0.x);
        const float s = det * (1.0f / 6.0f);

        atomicAdd(&g_w[i0], s);   // REDG.F32, no return
        atomicAdd(&g_w[i1], s);
        atomicAdd(&g_w[i2], s);
    }
}

// ---------------- Phase 2: dense dot  out[v] = sum_n w[n]*vals[n][v] ---------
// One node per thread: 3 independent coalesced loads (w, vals4[2n], vals4[2n+1]),
// 1M threads of TLP, minimal registers.
__global__ __launch_bounds__(256) void phase2_kernel(
    const float4* __restrict__ vals4,  // 2*N_NODES float4s
    float* __restrict__ out,
    int n_nodes, int nblocks)
{
    const int n = blockIdx.x * 256 + threadIdx.x;

    float4 accA = make_float4(0.f, 0.f, 0.f, 0.f);
    float4 accB = make_float4(0.f, 0.f, 0.f, 0.f);

    if (n < n_nodes) {
        const float  wn = g_w[n];
        const float4 a  = vals4[2 * n];
        const float4 b  = vals4[2 * n + 1];
        g_w[n] = 0.0f;  // reset for next replay (this thread owns this slot)
        accA.x = wn * a.x;  accA.y = wn * a.y;
        accA.z = wn * a.z;  accA.w = wn * a.w;
        accB.x = wn * b.x;  accB.y = wn * b.y;
        accB.z = wn * b.z;  accB.w = wn * b.w;
    }

    // Full warp xor-reduce of all 8 accumulators.
#pragma unroll
    for (int off = 16; off >= 1; off >>= 1) {
        accA.x += __shfl_xor_sync(0xFFFFFFFFu, accA.x, off);
        accA.y += __shfl_xor_sync(0xFFFFFFFFu, accA.y, off);
        accA.z += __shfl_xor_sync(0xFFFFFFFFu, accA.z, off);
        accA.w += __shfl_xor_sync(0xFFFFFFFFu, accA.w, off);
        accB.x += __shfl_xor_sync(0xFFFFFFFFu, accB.x, off);
        accB.y += __shfl_xor_sync(0xFFFFFFFFu, accB.y, off);
        accB.z += __shfl_xor_sync(0xFFFFFFFFu, accB.z, off);
        accB.w += __shfl_xor_sync(0xFFFFFFFFu, accB.w, off);
    }

    __shared__ float sred[8][8];  // [warp][value]
    const int warp = threadIdx.x >> 5;
    const int lane = threadIdx.x & 31;
    if (lane == 0) {
        sred[warp][0] = accA.x;  sred[warp][1] = accA.y;
        sred[warp][2] = accA.z;  sred[warp][3] = accA.w;
        sred[warp][4] = accB.x;  sred[warp][5] = accB.y;
        sred[warp][6] = accB.z;  sred[warp][7] = accB.w;
    }
    __syncthreads();

    if (threadIdx.x < 8) {
        float sum = 0.0f;
#pragma unroll
        for (int w = 0; w < 8; w++) sum += sred[w][threadIdx.x];
        atomicAdd(&g_acc[threadIdx.x], (double)sum);
    }

    // Last-block-done: fused finalize + state reset (replay-deterministic).
    __shared__ bool is_last;
    __threadfence();
    if (threadIdx.x == 0) {
        unsigned int old = atomicInc(&g_count, (unsigned int)(nblocks - 1));
        is_last = (old == (unsigned int)(nblocks - 1));
    }
    __syncthreads();

    if (is_last && threadIdx.x < 8) {
        const double val = atomicAdd(&g_acc[threadIdx.x], 0.0);
        out[threadIdx.x] = (float)val;
        g_acc[threadIdx.x] = 0.0;
    }
}

extern "C" void kernel_launch(void* const* d_in, const int* in_sizes, int n_in,
                              void* d_out, int out_size) {
    const float* nodal_values = (const float*)d_in[0];
    const float* coords       = (const float*)d_in[1];
    const int*   elements     = (const int*)d_in[2];
    float* out = (float*)d_out;

    const int n_elements = in_sizes[2] / 3;
    const int n_nodes    = in_sizes[1] / 2;

    phase1_kernel<<<2048, 256>>>(coords, elements, n_elements);

    const int p2_blocks = (n_nodes + 255) / 256;  // 3907 for 1M nodes
    phase2_kernel<<<p2_blocks, 256>>>(
        reinterpret_cast<const float4*>(nodal_values), out, n_nodes, p2_blocks);
}

// round 7
// speedup vs baseline: 1.1016x; 1.1016x over previous
#include <cuda_runtime.h>

// Per-node weight accumulator. Zero at module load; phase 2 re-zeroes after
// consuming, so every graph replay starts from zeros.
__device__ float g_w[4 * 1024 * 1024];
__device__ double g_acc[8];
__device__ unsigned int g_count;

// ---------------- Phase 1: per-element det(J) scattered to node weights -----
// Grid-stride; atomics interleaved per iteration pipeline under the next
// iteration's loads. Element stream uses __ldcs (evict-first) to keep L1
// capacity for the random coord gathers. The 1/6 factor is folded into
// the finalize.
__global__ __launch_bounds__(256) void phase1_kernel(
    const float* __restrict__ coords,    // (N_NODES, 2)
    const int*   __restrict__ elements,  // (E, 3)
    int n_elements)
{
    const int stride = gridDim.x * blockDim.x;
    for (int e = blockIdx.x * blockDim.x + threadIdx.x; e < n_elements; e += stride) {
        const int i0 = __ldcs(elements + 3 * e + 0);
        const int i1 = __ldcs(elements + 3 * e + 1);
        const int i2 = __ldcs(elements + 3 * e + 2);

        const float2 c0 = *reinterpret_cast<const float2*>(coords + 2 * i0);
        const float2 c1 = *reinterpret_cast<const float2*>(coords + 2 * i1);
        const float2 c2 = *reinterpret_cast<const float2*>(coords + 2 * i2);

        // det(J) for Tri3 (scale by 1/6 deferred to finalize).
        const float det = (c1.x - c0.x) * (c2.y - c0.y)
                        - (c1.y - c0.y) * (c2.x - c0.x);

        atomicAdd(&g_w[i0], det);   // REDG.F32, no return
        atomicAdd(&g_w[i1], det);
        atomicAdd(&g_w[i2], det);
    }
}

// ---------------- Phase 2: dense dot  out[v] = (1/6) sum_n w[n]*vals[n][v] ---
// nodal_values viewed as 2*N float4s. Even float4 j -> v0..3 of node j/2,
// odd j -> v4..7. Thread parity == j parity (stride is even), so each thread
// always accumulates the same 4-value group; xor-reduce preserves parity.
static const int P2_UNROLL = 8;

__global__ __launch_bounds__(256) void phase2_kernel(
    const float4* __restrict__ vals4,  // 2*N_NODES float4s
    float* __restrict__ out,
    int n_f4, int nblocks)
{
    const int T = nblocks * 256;  // total threads (even)
    const int t = blockIdx.x * 256 + threadIdx.x;

    // Front-batched guarded loads: up to 16 independent loads in flight.
    float  wreg[P2_UNROLL];
    float4 vreg[P2_UNROLL];
#pragma unroll
    for (int k = 0; k < P2_UNROLL; k++) {
        const int j = t + k * T;
        if (j < n_f4) {
            wreg[k] = g_w[j >> 1];
            vreg[k] = vals4[j];
        } else {
            wreg[k] = 0.0f;
            vreg[k] = make_float4(0.f, 0.f, 0.f, 0.f);
        }
    }

    // Zero w for next replay: even threads own even j = 2n -> every node once.
    if ((t & 1) == 0) {
#pragma unroll
        for (int k = 0; k < P2_UNROLL; k++) {
            const int j = t + k * T;
            if (j < n_f4) g_w[j >> 1] = 0.0f;
        }
    }

    float4 acc = make_float4(0.f, 0.f, 0.f, 0.f);
#pragma unroll
    for (int k = 0; k < P2_UNROLL; k++) {
        acc.x += wreg[k] * vreg[k].x;
        acc.y += wreg[k] * vreg[k].y;
        acc.z += wreg[k] * vreg[k].z;
        acc.w += wreg[k] * vreg[k].w;
    }

    // Parity-preserving xor reduction (offsets 16,8,4,2): lane0 = even lanes
    // (v0-3), lane1 = odd lanes (v4-7).
#pragma unroll
    for (int off = 16; off >= 2; off >>= 1) {
        acc.x += __shfl_xor_sync(0xFFFFFFFFu, acc.x, off);
        acc.y += __shfl_xor_sync(0xFFFFFFFFu, acc.y, off);
        acc.z += __shfl_xor_sync(0xFFFFFFFFu, acc.z, off);
        acc.w += __shfl_xor_sync(0xFFFFFFFFu, acc.w, off);
    }

    __shared__ float4 sred[8][2];  // [warp][parity]
    const int warp = threadIdx.x >> 5;
    const int lane = threadIdx.x & 31;
    if (lane < 2) sred[warp][lane] = acc;
    __syncthreads();

    if (threadIdx.x < 2) {
        const int p = threadIdx.x;  // 0 -> v0-3, 1 -> v4-7
        float4 sum = make_float4(0.f, 0.f, 0.f, 0.f);
#pragma unroll
        for (int w = 0; w < 8; w++) {
            sum.x += sred[w][p].x;  sum.y += sred[w][p].y;
            sum.z += sred[w][p].z;  sum.w += sred[w][p].w;
        }
        atomicAdd(&g_acc[4 * p + 0], (double)sum.x);
        atomicAdd(&g_acc[4 * p + 1], (double)sum.y);
        atomicAdd(&g_acc[4 * p + 2], (double)sum.z);
        atomicAdd(&g_acc[4 * p + 3], (double)sum.w);
    }

    // Last-block-done: fused finalize + state reset (replay-deterministic).
    __shared__ bool is_last;
    __threadfence();
    if (threadIdx.x == 0) {
        unsigned int old = atomicInc(&g_count, (unsigned int)(nblocks - 1));
        is_last = (old == (unsigned int)(nblocks - 1));
    }
    __syncthreads();

    if (is_last && threadIdx.x < 8) {
        const double val = atomicAdd(&g_acc[threadIdx.x], 0.0);
        out[threadIdx.x] = (float)(val * (1.0 / 6.0));  // fold quad weight here
        g_acc[threadIdx.x] = 0.0;
    }
}

extern "C" void kernel_launch(void* const* d_in, const int* in_sizes, int n_in,
                              void* d_out, int out_size) {
    const float* nodal_values = (const float*)d_in[0];
    const float* coords       = (const float*)d_in[1];
    const int*   elements     = (const int*)d_in[2];
    float* out = (float*)d_out;

    const int n_elements = in_sizes[2] / 3;
    const int n_nodes    = in_sizes[1] / 2;
    const int n_f4       = n_nodes * 2;

    phase1_kernel<<<2048, 256>>>(coords, elements, n_elements);

    const int p2_blocks = (n_f4 + 256 * P2_UNROLL - 1) / (256 * P2_UNROLL);  // 977
    phase2_kernel<<<p2_blocks, 256>>>(
        reinterpret_cast<const float4*>(nodal_values), out, n_f4, p2_blocks);
}